// round 11
// baseline (speedup 1.0000x reference)
#include <cuda_runtime.h>
#include <cstdint>

#define TSTEPS 2048
#define BATCH  32
#define EDIM   512
#define HDIM   512
#define C4     2048
#define NCTA   128

typedef unsigned long long ull;

__device__ float    g_xp[(size_t)TSTEPS * C4 * BATCH];   // [t][c][b]
__device__ float    g_h[2][HDIM * BATCH];                // [col][b]
__device__ unsigned g_flag[NCTA];                        // h publish progress per CTA

__device__ __forceinline__ ull ffma2(ull a, ull b, ull c) {
    ull d;
    asm("fma.rn.f32x2 %0, %1, %2, %3;" : "=l"(d) : "l"(a), "l"(b), "l"(c));
    return d;
}
__device__ __forceinline__ ull fadd2(ull a, ull b) {
    ull d;
    asm("add.rn.f32x2 %0, %1, %2;" : "=l"(d) : "l"(a), "l"(b));
    return d;
}
__device__ __forceinline__ ull pack2(float lo, float hi) {
    return ((ull)__float_as_uint(hi) << 32) | (ull)__float_as_uint(lo);
}
__device__ __forceinline__ float hsum2(ull u) {
    return __uint_as_float((unsigned)u) + __uint_as_float((unsigned)(u >> 32));
}
__device__ __forceinline__ float sigf(float x) { return 1.0f / (1.0f + __expf(-x)); }
__device__ __forceinline__ float tanhf_fast(float x) {
    return __fmaf_rn(2.0f, sigf(2.0f * x), -1.0f);
}

// ---------------------------------------------------------------------------
__global__ void k_init() {
    int i = blockIdx.x * blockDim.x + threadIdx.x;
    if (i < 2 * HDIM * BATCH) ((float*)g_h)[i] = 0.0f;
    if (i < NCTA) g_flag[i] = 0u;
}

// ---------------------------------------------------------------------------
// Phase 1 (R7 version — best measured): xp = emb @ [Wix|Wfx|Wgx|Wox] + b.
// A resident swizzled (64KB); W streamed in 16 double-buffered 32-k chunks,
// layout [k2][c] k-parity packed; broadcast ulonglong2 reads in the hot loop.
// ---------------------------------------------------------------------------
__global__ void __launch_bounds__(256, 2) k_xproj(
    const float* __restrict__ emb,
    const float* __restrict__ wxi, const float* __restrict__ wxf,
    const float* __restrict__ wxg, const float* __restrict__ wxo,
    const float* __restrict__ bi,  const float* __restrict__ bf,
    const float* __restrict__ bg,  const float* __restrict__ bo)
{
    extern __shared__ float sm[];
    float2*             a2 = (float2*)sm;                        // [256 k2][32 b] swizzled
    unsigned long long* w2 = (unsigned long long*)(sm + 16384);  // 2 bufs x [16 k2][128 c]

    const int tid  = threadIdx.x;
    const int lane = tid & 31;
    const int wrp  = tid >> 5;
    const int t    = blockIdx.y;
    const int ct   = blockIdx.x;
    const int gate = ct >> 2;
    const int co   = (ct & 3) * 128;

    const float* W  = (gate == 0) ? wxi : (gate == 1) ? wxf : (gate == 2) ? wxg : wxo;
    const float* bs = (gate == 0) ? bi  : (gate == 1) ? bf  : (gate == 2) ? bg  : bo;

    // Stage A: thread owns k2 = tid for all 32 b (coalesced LDG.64 per b).
    {
        const float2* src = (const float2*)(emb + (size_t)t * (BATCH * EDIM));
        const int k2 = tid, sw = k2 & 31;
        #pragma unroll
        for (int b = 0; b < 32; b++)
            a2[k2 * 32 + (b ^ sw)] = src[b * 256 + k2];
    }

    // W staging: thread (wrp,lane), i in {0,1}: k2l = wrp*2+i, cols co+lane*4..+3.
    float4 r0[2], r1[2];
    #pragma unroll
    for (int i = 0; i < 2; i++) {
        int k2l = wrp * 2 + i;
        const float* Wp = &W[(size_t)(k2l * 2) * HDIM + co + lane * 4];
        r0[i] = *(const float4*)Wp;
        r1[i] = *(const float4*)(Wp + HDIM);
    }
    #pragma unroll
    for (int i = 0; i < 2; i++) {
        int k2l = wrp * 2 + i;
        ulonglong2* dst = (ulonglong2*)&w2[k2l * 128 + lane * 4];
        dst[0] = make_ulonglong2(pack2(r0[i].x, r1[i].x), pack2(r0[i].y, r1[i].y));
        dst[1] = make_ulonglong2(pack2(r0[i].z, r1[i].z), pack2(r0[i].w, r1[i].w));
    }
    __syncthreads();

    ull acc[16];
    #pragma unroll
    for (int j = 0; j < 16; j++) acc[j] = 0ull;

    const ull* a2u = (const ull*)a2;
    int p = 0;
    for (int kc = 0; kc < 16; kc++) {
        if (kc < 15) {
            #pragma unroll
            for (int i = 0; i < 2; i++) {
                int k2l = wrp * 2 + i;
                const float* Wp = &W[(size_t)((kc + 1) * 32 + k2l * 2) * HDIM + co + lane * 4];
                r0[i] = *(const float4*)Wp;
                r1[i] = *(const float4*)(Wp + HDIM);
            }
        }
        const ull* wu = w2 + p * 2048;
        const int k2g0 = kc * 16;
        #pragma unroll
        for (int k2l = 0; k2l < 16; k2l++) {
            int kA = k2g0 + k2l;
            ull h0 = a2u[kA * 32 + (lane ^ (kA & 31))];
            #pragma unroll
            for (int jj = 0; jj < 16; jj += 2) {
                ulonglong2 wv = *(const ulonglong2*)&wu[k2l * 128 + wrp * 16 + jj];
                acc[jj]     = ffma2(h0, wv.x, acc[jj]);
                acc[jj + 1] = ffma2(h0, wv.y, acc[jj + 1]);
            }
        }
        if (kc < 15) {
            ull* wd = w2 + (p ^ 1) * 2048;
            #pragma unroll
            for (int i = 0; i < 2; i++) {
                int k2l = wrp * 2 + i;
                ulonglong2* dst = (ulonglong2*)&wd[k2l * 128 + lane * 4];
                dst[0] = make_ulonglong2(pack2(r0[i].x, r1[i].x), pack2(r0[i].y, r1[i].y));
                dst[1] = make_ulonglong2(pack2(r0[i].z, r1[i].z), pack2(r0[i].w, r1[i].w));
            }
        }
        __syncthreads();
        p ^= 1;
    }

    float* xp = g_xp + ((size_t)t * C4 + (size_t)gate * 512 + co) * 32;
    #pragma unroll
    for (int j = 0; j < 16; j++) {
        int c = wrp * 16 + j;
        float s = hsum2(acc[j]) + __ldg(&bs[co + c]);
        xp[(size_t)c * 32 + lane] = s;
    }
}

// ---------------------------------------------------------------------------
// Phase 2: persistent recurrence with FLAG DATAFLOW (no global barrier).
// flag[c] = s  <=>  CTA c published h for step s (in buffer s&1).
// Warp w waits only on flags of its 8 producer CTAs, then runs the pipelined
// outer-product matmul. Safety: ping-pong suffices because writing h(t+1)
// requires having read all of h(t), whose publication required every CTA to
// have finished reading h(t-1) (the same buffer being overwritten).
// ---------------------------------------------------------------------------
#define LOADC(kc, A0, A1)                                                  \
    _Pragma("unroll")                                                      \
    for (int k = 0; k < 8; k++) {                                          \
        asm("ld.global.cg.v2.u64 {%0,%1}, [%2];"                           \
            : "=l"(A0[k]), "=l"(A1[k])                                     \
            : "l"(hb + ((kc) * 8 + k) * 32));                              \
    }

#define COMPC(kc, A0, A1)                                                  \
    _Pragma("unroll")                                                      \
    for (int k = 0; k < 8; k++) {                                          \
        const ull* wp = whs + (size_t)(k0 + (kc) * 8 + k) * 16 + c_grp * 4;\
        ulonglong2 w01 = *(const ulonglong2*)wp;                           \
        ulonglong2 w23 = *(const ulonglong2*)(wp + 2);                     \
        acc[0] = ffma2(A0[k], w01.x, acc[0]);                              \
        acc[1] = ffma2(A1[k], w01.x, acc[1]);                              \
        acc[2] = ffma2(A0[k], w01.y, acc[2]);                              \
        acc[3] = ffma2(A1[k], w01.y, acc[3]);                              \
        acc[4] = ffma2(A0[k], w23.x, acc[4]);                              \
        acc[5] = ffma2(A1[k], w23.x, acc[5]);                              \
        acc[6] = ffma2(A0[k], w23.y, acc[6]);                              \
        acc[7] = ffma2(A1[k], w23.y, acc[7]);                              \
    }

__global__ void __launch_bounds__(512, 1) k_rec(
    const float* __restrict__ whi, const float* __restrict__ whf,
    const float* __restrict__ whg, const float* __restrict__ who,
    float* __restrict__ out)
{
    extern __shared__ ull sr[];
    ull*   whs = sr;                     // [512 k][16 lc] dup'd      (8192 ull)
    ull*   red = sr + 8192;              // [16 w][16 c x 18]         (4608 ull)
    ull*   sgu = sr + 12800;             // [16 c][16 bp]             (256 ull)
    float* sgf = (float*)sgu;
    float* ost = (float*)(sr + 13056);   // [32 b][4 hu]              (64 ull)

    const int tid  = threadIdx.x;
    const int lane = tid & 31;
    const int wrp  = tid >> 5;           // 0..15
    const int cta  = blockIdx.x;

    for (int i = tid; i < 8192; i += 512) {
        int k = i >> 4, lc = i & 15;
        int g = lc >> 2, hu = lc & 3;
        const float* Wp = (g == 0) ? whi : (g == 1) ? whf : (g == 2) ? whg : who;
        float w = Wp[(size_t)k * HDIM + cta * 4 + hu];
        whs[i] = pack2(w, w);
    }
    __syncthreads();

    const int b_grp = lane >> 2;
    const int c_grp = lane & 3;
    const int k0    = wrp * 32;
    const int hu_g  = tid >> 5;          // gate phase (tid<128)
    const int b_g   = tid & 31;
    const int cl_r  = tid >> 4;          // reduce phase (tid<256)
    const int bp_r  = tid & 15;
    float c_state = 0.0f;

    // Each warp's k-slice [wrp*32, wrp*32+32) covers h cols from producer
    // CTAs [wrp*8, wrp*8+8). Lane l<8 polls producer wrp*8+l.
    const unsigned* myflag = (lane < 8) ? &g_flag[wrp * 8 + lane] : &g_flag[wrp * 8];

    for (int t = 0; t < TSTEPS; t++) {
        const int pin = t & 1;
        const float* hb = g_h[pin] + k0 * 32 + b_grp * 4;

        // xp prefetch (independent of h; consumed in reduce phase).
        float2 xv = make_float2(0.f, 0.f);
        if (tid < 256) {
            int g = cl_r >> 2, hu = cl_r & 3;
            xv = __ldcg((const float2*)&g_xp[
                ((size_t)t * C4 + (size_t)(g * 512 + cta * 4 + hu)) * 32 + bp_r * 2]);
        }

        // Fine-grained wait: this warp's 8 producers must have published step t.
        if (lane < 8) {
            unsigned v;
            do {
                asm volatile("ld.acquire.gpu.global.u32 %0, [%1];"
                             : "=r"(v) : "l"(myflag) : "memory");
            } while (v < (unsigned)t);
        }
        __syncwarp();

        ull acc[8];
        #pragma unroll
        for (int j = 0; j < 8; j++) acc[j] = 0ull;

        // Software-pipelined matmul: chunks of 8 k, distance-1 prefetch.
        {
            ull pa0[8], pa1[8], pb0[8], pb1[8];
            LOADC(0, pa0, pa1);
            LOADC(1, pb0, pb1);
            COMPC(0, pa0, pa1);
            LOADC(2, pa0, pa1);
            COMPC(1, pb0, pb1);
            LOADC(3, pb0, pb1);
            COMPC(2, pa0, pa1);
            COMPC(3, pb0, pb1);
        }

        #pragma unroll
        for (int j = 0; j < 4; j++) {
            ulonglong2 v;
            v.x = acc[j * 2];
            v.y = acc[j * 2 + 1];
            *(ulonglong2*)&red[wrp * 288 + (c_grp * 4 + j) * 18 + b_grp * 2] = v;
        }
        __syncthreads();

        // Parallel packed reduce: 256 threads, one (lc, b-pair) each.
        if (tid < 256) {
            ull v[16];
            #pragma unroll
            for (int w = 0; w < 16; w++)
                v[w] = red[w * 288 + cl_r * 18 + bp_r];
            #pragma unroll
            for (int st = 8; st >= 1; st >>= 1)
                #pragma unroll
                for (int w = 0; w < st; w++) v[w] = fadd2(v[w], v[w + st]);
            sgu[cl_r * 16 + bp_r] = fadd2(v[0], pack2(xv.x, xv.y));
        }
        __syncthreads();

        if (tid < 128) {
            float s0 = sgf[(0 * 4 + hu_g) * 32 + b_g];
            float s1 = sgf[(1 * 4 + hu_g) * 32 + b_g];
            float s2 = sgf[(2 * 4 + hu_g) * 32 + b_g];
            float s3 = sgf[(3 * 4 + hu_g) * 32 + b_g];
            float ig = sigf(s0);
            float fg = sigf(s1);
            float gg = tanhf_fast(s2);
            float og = sigf(s3);
            c_state = fg * c_state + ig * gg;
            float hval = og * tanhf_fast(c_state);

            int col = cta * 4 + hu_g;
            __stcg(&((float*)g_h[pin ^ 1])[col * 32 + b_g], hval);
            ost[b_g * 4 + hu_g] = hval;
        }
        __syncthreads();   // h (.cg) + ost stores done CTA-wide

        // Publish: release-store carries the h stores (ordered via bar.sync).
        if (t < TSTEPS - 1 && tid == 0) {
            asm volatile("st.release.gpu.global.u32 [%0], %1;"
                         :: "l"(&g_flag[cta]), "r"((unsigned)(t + 1)) : "memory");
        }

        // out store overlaps other CTAs' publish/consume.
        if (tid >= 128 && tid < 160) {
            int b = tid - 128;
            float4 o4 = *(const float4*)&ost[b * 4];
            *(float4*)&out[(size_t)t * (BATCH * HDIM) + (size_t)b * HDIM + cta * 4] = o4;
        }
    }
}

// ---------------------------------------------------------------------------
extern "C" void kernel_launch(void* const* d_in, const int* in_sizes, int n_in,
                              void* d_out, int out_size) {
    const float* emb = (const float*)d_in[0];
    const float* wxi = (const float*)d_in[1];
    const float* whi = (const float*)d_in[2];
    const float* bi  = (const float*)d_in[3];
    const float* wxf = (const float*)d_in[4];
    const float* whf = (const float*)d_in[5];
    const float* bf  = (const float*)d_in[6];
    const float* wxg = (const float*)d_in[7];
    const float* whg = (const float*)d_in[8];
    const float* bg  = (const float*)d_in[9];
    const float* wxo = (const float*)d_in[10];
    const float* who = (const float*)d_in[11];
    const float* bo  = (const float*)d_in[12];
    float* out = (float*)d_out;

    cudaFuncSetAttribute(k_xproj, cudaFuncAttributeMaxDynamicSharedMemorySize, 98304);
    cudaFuncSetAttribute(k_rec,   cudaFuncAttributeMaxDynamicSharedMemorySize, 104960);

    k_xproj<<<dim3(16, TSTEPS), 256, 98304>>>(emb, wxi, wxf, wxg, wxo, bi, bf, bg, bo);
    k_init<<<128, 256>>>();
    k_rec<<<NCTA, 512, 104960>>>(whi, whf, whg, who, out);
}

// round 12
// speedup vs baseline: 1.7271x; 1.7271x over previous
#include <cuda_runtime.h>
#include <cstdint>

#define TSTEPS 2048
#define BATCH  32
#define EDIM   512
#define HDIM   512
#define C4     2048
#define NCTA   128

typedef unsigned long long ull;

__device__ float    g_xp[(size_t)TSTEPS * C4 * BATCH];   // [t][c][b]
__device__ float    g_h[2][HDIM * BATCH];                // ull idx k2*32+b = (h[2k2][b], h[2k2+1][b])
__device__ unsigned g_grp[8];                            // tree barrier: 16 CTAs per group
__device__ unsigned g_root;

__device__ __forceinline__ ull ffma2(ull a, ull b, ull c) {
    ull d;
    asm("fma.rn.f32x2 %0, %1, %2, %3;" : "=l"(d) : "l"(a), "l"(b), "l"(c));
    return d;
}
__device__ __forceinline__ ull fadd2(ull a, ull b) {
    ull d;
    asm("add.rn.f32x2 %0, %1, %2;" : "=l"(d) : "l"(a), "l"(b));
    return d;
}
__device__ __forceinline__ ull pack2(float lo, float hi) {
    return ((ull)__float_as_uint(hi) << 32) | (ull)__float_as_uint(lo);
}
__device__ __forceinline__ ull dup2(float v) {
    ull d; unsigned u = __float_as_uint(v);
    asm("mov.b64 %0, {%1, %1};" : "=l"(d) : "r"(u));
    return d;
}
__device__ __forceinline__ float hsum2(ull u) {
    return __uint_as_float((unsigned)u) + __uint_as_float((unsigned)(u >> 32));
}
__device__ __forceinline__ float sigf(float x) { return 1.0f / (1.0f + __expf(-x)); }
__device__ __forceinline__ float tanhf_fast(float x) {
    return __fmaf_rn(2.0f, sigf(2.0f * x), -1.0f);
}

// ---------------------------------------------------------------------------
__global__ void k_init() {
    int i = blockIdx.x * blockDim.x + threadIdx.x;
    if (i < 2 * HDIM * BATCH) ((float*)g_h)[i] = 0.0f;
    if (i < 8) g_grp[i] = 0u;
    if (i == 8) g_root = 0u;
}

// ---------------------------------------------------------------------------
// Phase 1: xp[t][c][b] = sum_k emb[t][b][k] * Wx[k][c] + bias[c]
// Outer-product microkernel: warp = 32b x 16c, thread = 4b x 4c.
// A staged once into smem [k][36-pad] (one 128B-unique LDS.128-pair per
// warp-k). W streamed undup'd as float4 (4 c per LDS.128), duplicated in
// registers via mov.b64 {r,r} (ALU pipe). 32 double-buffered 16-k chunks.
// smem = 18432 + 2*2112 floats = 90624 B -> 2 CTAs/SM.
// ---------------------------------------------------------------------------
__global__ void __launch_bounds__(256, 2) k_xproj(
    const float* __restrict__ emb,
    const float* __restrict__ wxi, const float* __restrict__ wxf,
    const float* __restrict__ wxg, const float* __restrict__ wxo,
    const float* __restrict__ bi,  const float* __restrict__ bf,
    const float* __restrict__ bg,  const float* __restrict__ bo)
{
    extern __shared__ float sm[];
    float* a2 = sm;                      // [512 k][36] floats (pad: 144B rows, 16B aligned)
    float* ws = sm + 18432;              // 2 bufs x [16 k][132] floats

    const int tid  = threadIdx.x;
    const int lane = tid & 31;
    const int wrp  = tid >> 5;           // 0..7
    const int t    = blockIdx.y;
    const int ct   = blockIdx.x;
    const int gate = ct >> 2;
    const int co   = (ct & 3) * 128;

    const float* W  = (gate == 0) ? wxi : (gate == 1) ? wxf : (gate == 2) ? wxg : wxo;
    const float* bs = (gate == 0) ? bi  : (gate == 1) ? bf  : (gate == 2) ? bg  : bo;

    const int b_grp = lane >> 2;         // 0..7 -> b = b_grp*4 .. +3
    const int c_grp = lane & 3;          // 0..3 -> c = wrp*16 + c_grp*4 .. +3

    // Stage A: emb[t][b][k] -> a2[k][b] (padded rows). Coalesced float4 loads.
    {
        const float* src = emb + (size_t)t * (BATCH * EDIM);
        const int b  = tid >> 3;
        const int qb = tid & 7;
        #pragma unroll
        for (int i = 0; i < 16; i++) {
            int q = qb + 8 * i;          // k-quad 0..127
            float4 v = *(const float4*)&src[b * EDIM + q * 4];
            int k = q * 4;
            a2[(k + 0) * 36 + b] = v.x;
            a2[(k + 1) * 36 + b] = v.y;
            a2[(k + 2) * 36 + b] = v.z;
            a2[(k + 3) * 36 + b] = v.w;
        }
    }

    // W chunk staging: thread handles kk = tid>>5 (+8), cols co + lane*4 .. +3.
    float4 pre[2];
    #define XLOAD(kc)                                                          \
        _Pragma("unroll")                                                      \
        for (int i = 0; i < 2; i++)                                            \
            pre[i] = *(const float4*)&W[(size_t)((kc) * 16 + (tid >> 5) + 8 * i) * HDIM + co + lane * 4];
    #define XSTORE(buf)                                                        \
        _Pragma("unroll")                                                      \
        for (int i = 0; i < 2; i++)                                            \
            *(float4*)&(buf)[((tid >> 5) + 8 * i) * 132 + lane * 4] = pre[i];

    XLOAD(0);
    XSTORE(ws);
    __syncthreads();

    ull acc[8];
    #pragma unroll
    for (int j = 0; j < 8; j++) acc[j] = 0ull;

    const ull* a2u = (const ull*)a2;     // row = 18 ull
    int p = 0;
    for (int kc = 0; kc < 32; kc++) {
        if (kc < 31) { XLOAD(kc + 1); }
        const float* wb = ws + p * 2112;
        #pragma unroll
        for (int k = 0; k < 16; k++) {
            int kg = kc * 16 + k;
            ulonglong2 av = *(const ulonglong2*)&a2u[kg * 18 + b_grp * 2];
            float4 wv = *(const float4*)&wb[k * 132 + (wrp * 4 + c_grp) * 4];
            ull w0 = dup2(wv.x), w1 = dup2(wv.y), w2 = dup2(wv.z), w3 = dup2(wv.w);
            acc[0] = ffma2(av.x, w0, acc[0]);
            acc[1] = ffma2(av.y, w0, acc[1]);
            acc[2] = ffma2(av.x, w1, acc[2]);
            acc[3] = ffma2(av.y, w1, acc[3]);
            acc[4] = ffma2(av.x, w2, acc[4]);
            acc[5] = ffma2(av.y, w2, acc[5]);
            acc[6] = ffma2(av.x, w3, acc[6]);
            acc[7] = ffma2(av.y, w3, acc[7]);
        }
        if (kc < 31) { XSTORE(ws + (p ^ 1) * 2112); }
        __syncthreads();
        p ^= 1;
    }

    // Epilogue: add bias, coalesced 16B stores into xp[t][c][b].
    float* xp = g_xp + ((size_t)t * C4 + (size_t)gate * 512 + co) * 32;
    #pragma unroll
    for (int j = 0; j < 4; j++) {
        int c = wrp * 16 + c_grp * 4 + j;
        float bv = __ldg(&bs[co + c]);
        ull bd = dup2(bv);
        ulonglong2 o;
        o.x = fadd2(acc[j * 2],     bd);
        o.y = fadd2(acc[j * 2 + 1], bd);
        *(ulonglong2*)&xp[(size_t)c * 32 + b_grp * 4] = o;
    }
    #undef XLOAD
    #undef XSTORE
}

// ---------------------------------------------------------------------------
// Phase 2: persistent recurrence (VERBATIM the 15967us-measured version).
// 128 CTAs x 512 threads; tree barrier (8 groups x 16 CTAs) acq_rel/release;
// front-batched h loads; parallel packed reduce; no threadfence.
// ---------------------------------------------------------------------------
__global__ void __launch_bounds__(512, 1) k_rec(
    const float* __restrict__ whi, const float* __restrict__ whf,
    const float* __restrict__ whg, const float* __restrict__ who,
    float* __restrict__ out)
{
    extern __shared__ float smr[];
    float2* whs   = (float2*)smr;                         // [16 lc][256 k2]
    float*  ost   = smr + 8192;                           // [32 b][4 hu]
    float*  sgate = smr + 8320;                           // [16 lc][32 b]
    ull*    red   = (ull*)(smr + 8832);                   // [16 w][16 lc][32 b]

    const int tid  = threadIdx.x;
    const int lane = tid & 31;
    const int wrp  = tid >> 5;       // 0..15
    const int cta  = blockIdx.x;

    for (int i = tid; i < 16 * 256; i += 512) {
        int lc = i >> 8, k2 = i & 255;
        int gate = lc >> 2, hu = lc & 3;
        const float* Wp = (gate == 0) ? whi : (gate == 1) ? whf : (gate == 2) ? whg : who;
        int col = cta * 4 + hu;
        whs[i] = make_float2(Wp[(size_t)(2 * k2) * HDIM + col],
                             Wp[(size_t)(2 * k2 + 1) * HDIM + col]);
    }
    __syncthreads();

    const int lc_r = tid >> 5;
    const int b_r  = tid & 31;
    const int b_g  = tid & 31;
    const int hu_g = tid >> 5;
    float c_state = 0.0f;

    const int k2base = wrp * 16;
    unsigned* grpp  = &g_grp[cta >> 4];
    unsigned* rootp = &g_root;

    for (int t = 0; t < TSTEPS; t++) {
        const int pin = t & 1;
        const ull* hin = (const ull*)g_h[pin];

        // Front-batch h loads (MLP 16) + this thread's xp element.
        ull hreg[16];
        #pragma unroll
        for (int i = 0; i < 16; i++)
            hreg[i] = __ldcg(&hin[(k2base + i) * 32 + lane]);
        float xpv;
        {
            int gate = lc_r >> 2, hu = lc_r & 3;
            xpv = __ldcg(&g_xp[((size_t)t * C4 + (size_t)(gate * 512 + cta * 4 + hu)) * 32 + b_r]);
        }

        ull acc[16];
        #pragma unroll
        for (int lc = 0; lc < 16; lc++) acc[lc] = 0ull;

        const ull* whu = (const ull*)whs;
        #pragma unroll
        for (int k2l = 0; k2l < 16; k2l += 2) {
            int k2 = k2base + k2l;
            #pragma unroll
            for (int lc = 0; lc < 16; lc++) {
                ulonglong2 wv = *(const ulonglong2*)&whu[lc * 256 + k2];
                acc[lc] = ffma2(hreg[k2l],     wv.x, acc[lc]);
                acc[lc] = ffma2(hreg[k2l + 1], wv.y, acc[lc]);
            }
        }

        #pragma unroll
        for (int lc = 0; lc < 16; lc++)
            red[(wrp * 16 + lc) * 32 + lane] = acc[lc];
        __syncthreads();

        // Parallel reduce: every thread owns one (lc, b).
        {
            ull v[16];
            #pragma unroll
            for (int w = 0; w < 16; w++) v[w] = red[(w * 16 + lc_r) * 32 + b_r];
            #pragma unroll
            for (int st = 8; st >= 1; st >>= 1)
                #pragma unroll
                for (int w = 0; w < st; w++) v[w] = fadd2(v[w], v[w + st]);
            sgate[lc_r * 32 + b_r] = hsum2(v[0]) + xpv;
        }
        __syncthreads();

        if (tid < 128) {
            float s0 = sgate[(0 * 4 + hu_g) * 32 + b_g];
            float s1 = sgate[(1 * 4 + hu_g) * 32 + b_g];
            float s2 = sgate[(2 * 4 + hu_g) * 32 + b_g];
            float s3 = sgate[(3 * 4 + hu_g) * 32 + b_g];
            float ig = sigf(s0);
            float fg = sigf(s1);
            float gg = tanhf_fast(s2);
            float og = sigf(s3);
            c_state = fg * c_state + ig * gg;
            float hval = og * tanhf_fast(c_state);

            int col = cta * 4 + hu_g;
            float* hout = (float*)g_h[pin ^ 1];
            __stcg(&hout[(col >> 1) * 64 + b_g * 2 + (col & 1)], hval);
            ost[b_g * 4 + hu_g] = hval;
        }
        __syncthreads();   // h + ost stores done CTA-wide

        if (t < TSTEPS - 1) {
            if (tid == 0) {
                unsigned old;
                asm volatile("atom.acq_rel.gpu.global.add.u32 %0, [%1], 1;"
                             : "=r"(old) : "l"(grpp) : "memory");
                if (old == 16u * (unsigned)(t + 1) - 1u) {
                    asm volatile("red.release.gpu.global.add.u32 [%0], 1;"
                                 :: "l"(rootp) : "memory");
                }
            }
            // Out store overlaps other CTAs' arrivals.
            if (tid < 32) {
                float4 o4 = *(const float4*)&ost[tid * 4];
                *(float4*)&out[(size_t)t * (BATCH * HDIM) + (size_t)tid * HDIM + cta * 4] = o4;
            }
            if (tid == 0) {
                unsigned target = 8u * (unsigned)(t + 1);
                unsigned v;
                do {
                    asm volatile("ld.acquire.gpu.global.u32 %0, [%1];"
                                 : "=r"(v) : "l"(rootp) : "memory");
                } while (v < target);
            }
            __syncthreads();
        } else {
            if (tid < 32) {
                float4 o4 = *(const float4*)&ost[tid * 4];
                *(float4*)&out[(size_t)t * (BATCH * HDIM) + (size_t)tid * HDIM + cta * 4] = o4;
            }
        }
    }
}

// ---------------------------------------------------------------------------
extern "C" void kernel_launch(void* const* d_in, const int* in_sizes, int n_in,
                              void* d_out, int out_size) {
    const float* emb = (const float*)d_in[0];
    const float* wxi = (const float*)d_in[1];
    const float* whi = (const float*)d_in[2];
    const float* bi  = (const float*)d_in[3];
    const float* wxf = (const float*)d_in[4];
    const float* whf = (const float*)d_in[5];
    const float* bf  = (const float*)d_in[6];
    const float* wxg = (const float*)d_in[7];
    const float* whg = (const float*)d_in[8];
    const float* bg  = (const float*)d_in[9];
    const float* wxo = (const float*)d_in[10];
    const float* who = (const float*)d_in[11];
    const float* bo  = (const float*)d_in[12];
    float* out = (float*)d_out;

    cudaFuncSetAttribute(k_xproj, cudaFuncAttributeMaxDynamicSharedMemorySize, 90624);
    cudaFuncSetAttribute(k_rec,   cudaFuncAttributeMaxDynamicSharedMemorySize, 100864);

    k_xproj<<<dim3(16, TSTEPS), 256, 90624>>>(emb, wxi, wxf, wxg, wxo, bi, bf, bg, bo);
    k_init<<<128, 256>>>();
    k_rec<<<NCTA, 512, 100864>>>(whi, whf, whg, who, out);
}